// round 14
// baseline (speedup 1.0000x reference)
#include <cuda_runtime.h>
#include <cuda_fp16.h>
#include <cstdint>
#include <cstddef>

// Problem constants
#define B_   16
#define N_   2048
#define E_   32768
#define D_   256
#define R_   8
#define L_   2

#define M_TOT (B_ * N_)       // 32768 rows
#define KDIM  256             // GEMM K = D
#define KT2   32              // K per stage
#define NT2   (KDIM / KT2)    // 8 stages
#define NBLK  18              // 16 relation col-blocks + 2 root col-blocks (128 each)

// ---------------- scratch (device globals; no allocation allowed) ----------
__device__ float g_y[M_TOT * D_];                    // layer-0 root output
__device__ __half g_xh[M_TOT * D_];                  // fp16 A
__device__ __half g_xw[(size_t)M_TOT * (R_ * D_)];   // 134 MB fp16 messages
// CSR by destination (rebuilt every call; deterministic row contents)
__device__ int g_degi[M_TOT];
__device__ int g_rowptr[M_TOT + 1];
__device__ int g_bsum[128];
__device__ int g_adj[B_ * E_];                       // (r<<15) | src_global
// pre-converted, pre-swizzled fp16 B tiles: [l(2)][kt(8)][bx(18)] x 8192 bytes
__device__ uint8_t g_Bh[L_ * NT2 * NBLK * 8192];

// ---------------- smem geometry for the GEMM -------------------------------
#define A_STRIDE  80                       // bytes per 32-fp16 A row (64B + 16 pad)
#define SA_BYTES  (128 * A_STRIDE)         // 10240 for A
#define OFF_B     SA_BYTES                 // 10240
#define STAGE     (OFF_B + 8192)           // 18432
#define NSTG      3
#define SMEM_DYN  (NSTG * STAGE + 128)     // 55424

// ---------------- PTX helpers ----------------------------------------------
__device__ __forceinline__ uint32_t smem_u32(const void* p) {
    uint32_t a;
    asm("{ .reg .u64 t; cvta.to.shared.u64 t, %1; cvt.u32.u64 %0, t; }"
        : "=r"(a) : "l"(p));
    return a;
}
__device__ __forceinline__ void ldsm4(uint32_t (&r)[4], uint32_t addr) {
    asm volatile("ldmatrix.sync.aligned.m8n8.x4.shared.b16 {%0,%1,%2,%3}, [%4];"
                 : "=r"(r[0]), "=r"(r[1]), "=r"(r[2]), "=r"(r[3]) : "r"(addr));
}
__device__ __forceinline__ void ldsm4t(uint32_t (&r)[4], uint32_t addr) {
    asm volatile("ldmatrix.sync.aligned.m8n8.x4.trans.shared.b16 {%0,%1,%2,%3}, [%4];"
                 : "=r"(r[0]), "=r"(r[1]), "=r"(r[2]), "=r"(r[3]) : "r"(addr));
}
__device__ __forceinline__ void mma16816h(float (&c)[4], const uint32_t (&a)[4],
                                          uint32_t b0, uint32_t b1) {
    asm volatile("mma.sync.aligned.m16n8k16.row.col.f32.f16.f16.f32 "
                 "{%0,%1,%2,%3}, {%4,%5,%6,%7}, {%8,%9}, {%0,%1,%2,%3};"
                 : "+f"(c[0]), "+f"(c[1]), "+f"(c[2]), "+f"(c[3])
                 : "r"(a[0]), "r"(a[1]), "r"(a[2]), "r"(a[3]), "r"(b0), "r"(b1));
}
__device__ __forceinline__ void cp16(uint32_t dst, const void* src) {
    asm volatile("cp.async.cg.shared.global [%0], [%1], 16;"
                 :: "r"(dst), "l"(src) : "memory");
}
__device__ __forceinline__ void sts4(uint32_t addr, uint32_t v) {
    asm volatile("st.shared.b32 [%0], %1;" :: "r"(addr), "r"(v) : "memory");
}
__device__ __forceinline__ void lds16(uint4& v, uint32_t addr) {
    asm volatile("ld.shared.v4.b32 {%0, %1, %2, %3}, [%4];"
                 : "=r"(v.x), "=r"(v.y), "=r"(v.z), "=r"(v.w) : "r"(addr));
}
__device__ __forceinline__ uint32_t cvt2h(float x0, float x1) {
    __half2 hh = __floats2half2_rn(x0, x1);
    return *(uint32_t*)&hh;
}

// ---------------- A convert (layer 0: gather + convert) ----------------------
__global__ void aconv0_kernel(const int* __restrict__ nodes,
                              const float* __restrict__ emb) {
    int idx = blockIdx.x * blockDim.x + threadIdx.x;   // M_TOT*32
    if (idx >= M_TOT * 32) return;
    int node = idx >> 5;
    int q = idx & 31;
    int v = nodes[node];
    const float4* src = (const float4*)(emb + (size_t)v * D_ + q * 8);
    float4 a = src[0];
    float4 b = src[1];
    uint4 h;
    h.x = cvt2h(a.x, a.y);
    h.y = cvt2h(a.z, a.w);
    h.z = cvt2h(b.x, b.y);
    h.w = cvt2h(b.z, b.w);
    *((uint4*)(g_xh) + idx) = h;
}

// ---------------- CSR build (single stream) ----------------------------------
__global__ void zero_counts() {
    int idx = blockIdx.x * blockDim.x + threadIdx.x;
    if (idx < M_TOT) g_degi[idx] = 0;
}
__global__ void count_deg(const int* __restrict__ edges) {
    int idx = blockIdx.x * blockDim.x + threadIdx.x;   // B_*E_/4
    if (idx >= (B_ * E_) / 4) return;
    int b = idx >> 13;
    int e4 = idx & ((E_ / 4) - 1);
    const int4 d4 = *(const int4*)(edges + (size_t)b * 2 * E_ + E_ + e4 * 4);
    int base = b * N_;
    atomicAdd(&g_degi[base + d4.x], 1);
    atomicAdd(&g_degi[base + d4.y], 1);
    atomicAdd(&g_degi[base + d4.z], 1);
    atomicAdd(&g_degi[base + d4.w], 1);
}
__global__ void scan1_kernel() {
    __shared__ int ws[8];
    int b = blockIdx.x, t = threadIdx.x, lane = t & 31, w = t >> 5;
    int i = b * 256 + t;
    int d = g_degi[i];
    int v = d;
#pragma unroll
    for (int off = 1; off < 32; off <<= 1) {
        int u = __shfl_up_sync(0xFFFFFFFFu, v, off);
        if (lane >= off) v += u;
    }
    if (lane == 31) ws[w] = v;
    __syncthreads();
    if (w == 0 && lane < 8) {
        int x = ws[lane];
#pragma unroll
        for (int off = 1; off < 8; off <<= 1) {
            int u = __shfl_up_sync(0xFFu, x, off);
            if (lane >= off) x += u;
        }
        ws[lane] = x;
    }
    __syncthreads();
    int incl = v + (w > 0 ? ws[w - 1] : 0);
    g_rowptr[i] = incl - d;
    if (t == 255) g_bsum[b] = incl;
}
__global__ void scan2_kernel() {
    __shared__ int ws[4];
    int t = threadIdx.x, lane = t & 31, w = t >> 5;
    int d = g_bsum[t];
    int v = d;
#pragma unroll
    for (int off = 1; off < 32; off <<= 1) {
        int u = __shfl_up_sync(0xFFFFFFFFu, v, off);
        if (lane >= off) v += u;
    }
    if (lane == 31) ws[w] = v;
    __syncthreads();
    if (w == 0 && lane < 4) {
        int x = ws[lane];
#pragma unroll
        for (int off = 1; off < 4; off <<= 1) {
            int u = __shfl_up_sync(0xFu, x, off);
            if (lane >= off) x += u;
        }
        ws[lane] = x;
    }
    __syncthreads();
    int incl = v + (w > 0 ? ws[w - 1] : 0);
    g_bsum[t] = incl - d;
    if (t == 127) g_rowptr[M_TOT] = incl;
}
__global__ void scan3_kernel() {
    int i = blockIdx.x * blockDim.x + threadIdx.x;
    g_rowptr[i] += g_bsum[blockIdx.x];
}
// fill using g_degi itself as a countdown cursor (no separate g_fill array)
__global__ void fill_adj(const int* __restrict__ edges,
                         const int* __restrict__ types) {
    int idx = blockIdx.x * blockDim.x + threadIdx.x;   // B_*E_/4
    if (idx >= (B_ * E_) / 4) return;
    int b = idx >> 13;
    int e4 = idx & ((E_ / 4) - 1);
    const int* eb = edges + (size_t)b * 2 * E_;
    const int4 s4 = *(const int4*)(eb + e4 * 4);
    const int4 d4 = *(const int4*)(eb + E_ + e4 * 4);
    const int4 r4 = *(const int4*)(types + (size_t)b * E_ + e4 * 4);
    int base = b * N_;
#pragma unroll
    for (int j = 0; j < 4; j++) {
        int src = (&s4.x)[j];
        int dst = (&d4.x)[j];
        int r = (&r4.x)[j];
        int gdst = base + dst;
        int pos = g_rowptr[gdst] + atomicSub(&g_degi[gdst], 1) - 1;
        g_adj[pos] = (r << 15) | (base + src);
    }
}

// Pre-convert + pre-swizzle W (BOTH layers) into ldmatrix-ready fp16 tiles.
__global__ void bconv_kernel(const float* __restrict__ W,
                             const float* __restrict__ Wroot) {
    int gid = blockIdx.x * blockDim.x + threadIdx.x;   // 2*8*18*512 = 147456
    if (gid >= L_ * NT2 * NBLK * 512) return;
    int tile = gid >> 9;
    int rem = gid & 511;
    int krow = rem >> 4;
    int gq = rem & 15;
    int l = tile / (NT2 * NBLK);
    int t2 = tile - l * (NT2 * NBLK);
    int kt = t2 / NBLK;
    int bx = t2 - kt * NBLK;
    int k = kt * KT2 + krow;
    int n0 = bx * 128 + gq * 8;
    const float* src = (n0 < 2048)
        ? W + (size_t)l * R_ * D_ * D_ + ((size_t)(n0 >> 8) << 16) + (size_t)k * 256 + (n0 & 255)
        : Wroot + (size_t)l * D_ * D_ + (size_t)k * 256 + (n0 - 2048);
    float4 v0 = ((const float4*)src)[0];
    float4 v1 = ((const float4*)src)[1];
    uint4 h;
    h.x = cvt2h(v0.x, v0.y);
    h.y = cvt2h(v0.z, v0.w);
    h.z = cvt2h(v1.x, v1.y);
    h.w = cvt2h(v1.z, v1.w);
    uint32_t off = (uint32_t)tile * 8192u + (uint32_t)krow * 256u +
                   ((uint32_t)(gq ^ (krow & 7)) << 4);
    *(uint4*)(g_Bh + off) = h;
}

// ---------------- atomic-free aggregation (fused epilogue) -------------------
// One warp per dst node; 4-edge unrolled MLP.
__global__ void __launch_bounds__(256)
aggregate_kernel(const __half* __restrict__ xw, float* __restrict__ Yin,
                 __half* __restrict__ xh_out) {
    int w = (blockIdx.x * blockDim.x + threadIdx.x) >> 5;
    int lane = threadIdx.x & 31;
    if (w >= M_TOT) return;
    int beg = g_rowptr[w];
    int end = g_rowptr[w + 1];

    float acc[8] = {0.f, 0.f, 0.f, 0.f, 0.f, 0.f, 0.f, 0.f};
    int p = beg;
    for (; p + 4 <= end; p += 4) {
        int e0 = __ldg(&g_adj[p]);
        int e1 = __ldg(&g_adj[p + 1]);
        int e2 = __ldg(&g_adj[p + 2]);
        int e3 = __ldg(&g_adj[p + 3]);
        uint4 v0 = __ldg((const uint4*)(xw + ((size_t)(e0 & 32767) * R_ + (e0 >> 15)) * D_) + lane);
        uint4 v1 = __ldg((const uint4*)(xw + ((size_t)(e1 & 32767) * R_ + (e1 >> 15)) * D_) + lane);
        uint4 v2 = __ldg((const uint4*)(xw + ((size_t)(e2 & 32767) * R_ + (e2 >> 15)) * D_) + lane);
        uint4 v3 = __ldg((const uint4*)(xw + ((size_t)(e3 & 32767) * R_ + (e3 >> 15)) * D_) + lane);
        const __half2* h0 = (const __half2*)&v0;
        const __half2* h1 = (const __half2*)&v1;
        const __half2* h2 = (const __half2*)&v2;
        const __half2* h3 = (const __half2*)&v3;
#pragma unroll
        for (int j = 0; j < 4; j++) {
            float2 f0 = __half22float2(h0[j]);
            float2 f1 = __half22float2(h1[j]);
            float2 f2 = __half22float2(h2[j]);
            float2 f3 = __half22float2(h3[j]);
            acc[2 * j]     += (f0.x + f1.x) + (f2.x + f3.x);
            acc[2 * j + 1] += (f0.y + f1.y) + (f2.y + f3.y);
        }
    }
    for (; p < end; p++) {
        int e0 = __ldg(&g_adj[p]);
        uint4 v0 = __ldg((const uint4*)(xw + ((size_t)(e0 & 32767) * R_ + (e0 >> 15)) * D_) + lane);
        const __half2* h0 = (const __half2*)&v0;
#pragma unroll
        for (int j = 0; j < 4; j++) {
            float2 f0 = __half22float2(h0[j]);
            acc[2 * j] += f0.x;
            acc[2 * j + 1] += f0.y;
        }
    }
    float idg = 1.0f / (float)((end - beg) > 1 ? (end - beg) : 1);
    float* yp = Yin + (size_t)w * D_ + lane * 8;
    float4 y0 = *(float4*)yp;
    float4 y1 = *(float4*)(yp + 4);
    y0.x += acc[0] * idg; y0.y += acc[1] * idg;
    y0.z += acc[2] * idg; y0.w += acc[3] * idg;
    y1.x += acc[4] * idg; y1.y += acc[5] * idg;
    y1.z += acc[6] * idg; y1.w += acc[7] * idg;
    if (xh_out) {
        uint4 h;
        h.x = cvt2h(fmaxf(y0.x, 0.f), fmaxf(y0.y, 0.f));
        h.y = cvt2h(fmaxf(y0.z, 0.f), fmaxf(y0.w, 0.f));
        h.z = cvt2h(fmaxf(y1.x, 0.f), fmaxf(y1.y, 0.f));
        h.w = cvt2h(fmaxf(y1.z, 0.f), fmaxf(y1.w, 0.f));
        *((uint4*)(xh_out + (size_t)w * D_) + lane) = h;
    } else {
        *(float4*)yp = y0;
        *(float4*)(yp + 4) = y1;
    }
}

// ---------------- warp-MMA GEMM ----------------------------------------------
// CTA: 128 rows x 128 cols, 256 threads (8 warps: 4M x 2N), 2 CTAs/SM.
// grid (18, 256): bx<16 -> fp16 to XW (smem-staged); bx>=16 -> Y = . + bias
__global__ void __launch_bounds__(256, 2)
rgcn_gemm_mma(const __half* __restrict__ Xh,
              const uint8_t* __restrict__ Bt,
              const float* __restrict__ bias,
              float* __restrict__ Y,
              __half* __restrict__ XW) {
    extern __shared__ uint8_t smem_raw[];
    const uint32_t sbase = (smem_u32(smem_raw) + 127u) & ~127u;

    const int tid = threadIdx.x;
    const int lane = tid & 31;
    const int wid = tid >> 5;
    const int warp_m = wid & 3;
    const int warp_n = wid >> 2;
    const int bx = blockIdx.x;
    const int m0 = blockIdx.y * 128;

    const int arow = tid >> 1;
    const int ac = tid & 1;
    const uint32_t a_sts = (uint32_t)arow * A_STRIDE + (uint32_t)ac * 32;
    const size_t a_goff = (size_t)(m0 + arow) * KDIM + ac * 16;

    const int g = lane >> 2;
    const int tc = lane & 3;

    uint32_t a_off[2];
#pragma unroll
    for (int mt = 0; mt < 2; mt++)
        a_off[mt] = (uint32_t)(warp_m * 32 + mt * 16 + (lane & 15)) * A_STRIDE +
                    (uint32_t)((lane >> 4) * 16);
    const uint32_t krow_base = (uint32_t)((lane & 7) + ((lane >> 3) & 1) * 8);
    uint32_t gg[4];
#pragma unroll
    for (int nt2 = 0; nt2 < 4; nt2++)
        gg[nt2] = (uint32_t)(((warp_n * 8 + nt2 * 2 + (lane >> 4)) ^ (lane & 7)) << 4);

    float c[2][8][4];
#pragma unroll
    for (int mt = 0; mt < 2; mt++)
#pragma unroll
        for (int nt = 0; nt < 8; nt++)
#pragma unroll
            for (int j = 0; j < 4; j++) c[mt][nt][j] = 0.f;

    auto issue_loads = [&](int kt, int s) {
        const uint32_t st = sbase + (uint32_t)s * STAGE;
        const uint8_t* bh = Bt + (size_t)(kt * NBLK + bx) * 8192 + tid * 16;
        cp16(st + OFF_B + tid * 16, bh);
        cp16(st + OFF_B + 4096 + tid * 16, bh + 4096);
        cp16(st + a_sts, Xh + a_goff + kt * KT2);
        cp16(st + a_sts + 16, Xh + a_goff + kt * KT2 + 8);
        asm volatile("cp.async.commit_group;" ::: "memory");
    };

    auto compute = [&](int s) {
        const uint32_t st = sbase + (uint32_t)s * STAGE;
#pragma unroll
        for (int k16 = 0; k16 < 2; k16++) {
            const uint32_t kb2 = (uint32_t)(k16 * 32);
            const uint32_t brow = (uint32_t)((k16 * 16) + krow_base) * 256u;
            uint32_t ah[2][4], bb[4][4];
            ldsm4(ah[0], st + a_off[0] + kb2);
            ldsm4(ah[1], st + a_off[1] + kb2);
#pragma unroll
            for (int nt2 = 0; nt2 < 4; nt2++)
                ldsm4t(bb[nt2], st + OFF_B + brow + gg[nt2]);
#pragma unroll
            for (int mt = 0; mt < 2; mt++)
#pragma unroll
                for (int nt = 0; nt < 8; nt++)
                    mma16816h(c[mt][nt], ah[mt], bb[nt >> 1][(nt & 1) * 2],
                              bb[nt >> 1][(nt & 1) * 2 + 1]);
        }
    };

    issue_loads(0, 0);
    issue_loads(1, 1);
    asm volatile("cp.async.wait_group 1;" ::: "memory");
    __syncthreads();

#pragma unroll 1
    for (int kt = 0; kt < NT2; kt++) {
        const int s = kt % NSTG;
        if (kt + 2 < NT2) issue_loads(kt + 2, (kt + 2) % NSTG);
        compute(s);
        if (kt + 1 < NT2) {
            asm volatile("cp.async.wait_group 1;" ::: "memory");
            __syncthreads();
        }
    }

    if (bx >= 16) {
        const int col0 = (bx - 16) * 128;
#pragma unroll
        for (int mt = 0; mt < 2; mt++) {
            const int row = m0 + warp_m * 32 + mt * 16 + g;
#pragma unroll
            for (int nt = 0; nt < 8; nt++) {
                const int col = col0 + warp_n * 64 + nt * 8 + tc * 2;
                const float b0 = bias[col];
                const float b1 = bias[col + 1];
                *(float2*)&Y[(size_t)row * D_ + col] =
                    make_float2(c[mt][nt][0] + b0, c[mt][nt][1] + b1);
                *(float2*)&Y[(size_t)(row + 8) * D_ + col] =
                    make_float2(c[mt][nt][2] + b0, c[mt][nt][3] + b1);
            }
        }
    } else {
        __syncthreads();
#pragma unroll
        for (int mt = 0; mt < 2; mt++) {
#pragma unroll
            for (int h = 0; h < 2; h++) {
                int lrow = warp_m * 32 + mt * 16 + h * 8 + g;
#pragma unroll
                for (int nt = 0; nt < 8; nt++) {
                    int gran = warp_n * 8 + nt;
                    uint32_t off = (uint32_t)lrow * 256 +
                                   ((uint32_t)(gran ^ (lrow & 7)) << 4) + tc * 4;
                    sts4(sbase + off, cvt2h(c[mt][nt][h * 2], c[mt][nt][h * 2 + 1]));
                }
            }
        }
        __syncthreads();
        __half* dst = XW + (size_t)m0 * (R_ * D_) + bx * 128;
#pragma unroll
        for (int p = 0; p < 8; p++) {
            int i = tid + p * 256;
            int row = i >> 4;
            int gran = i & 15;
            uint32_t soff = (uint32_t)row * 256 +
                            ((uint32_t)(gran ^ (row & 7)) << 4);
            uint4 v;
            lds16(v, sbase + soff);
            *(uint4*)(dst + (size_t)row * (R_ * D_) + gran * 8) = v;
        }
    }
}

// ---------------- launch (single stream, fully deterministic order) ----------
extern "C" void kernel_launch(void* const* d_in, const int* in_sizes, int n_in,
                              void* d_out, int out_size) {
    const int*   nodes = (const int*)d_in[0];
    const int*   edges = (const int*)d_in[1];
    const int*   types = (const int*)d_in[2];
    const float* emb   = (const float*)d_in[3];
    const float* W     = (const float*)d_in[4];
    const float* Wroot = (const float*)d_in[5];
    const float* bias  = (const float*)d_in[6];
    float* out = (float*)d_out;

    static bool attr_set = false;
    if (!attr_set) {
        cudaFuncSetAttribute(rgcn_gemm_mma,
                             cudaFuncAttributeMaxDynamicSharedMemorySize, SMEM_DYN);
        attr_set = true;
    }

    float* y0 = nullptr;
    __half *xw = nullptr, *xh = nullptr;
    uint8_t* bh = nullptr;
    cudaGetSymbolAddress((void**)&y0, g_y);
    cudaGetSymbolAddress((void**)&xw, g_xw);
    cudaGetSymbolAddress((void**)&xh, g_xh);
    cudaGetSymbolAddress((void**)&bh, g_Bh);
    uint8_t* bh1 = bh + (size_t)NT2 * NBLK * 8192;

    // prologue: weights, A convert, CSR build (all single stream)
    bconv_kernel<<<(L_ * NT2 * NBLK * 512) / 256, 256>>>(W, Wroot);
    aconv0_kernel<<<(M_TOT * 32) / 256, 256>>>(nodes, emb);
    zero_counts<<<M_TOT / 256, 256>>>();
    count_deg<<<(B_ * E_ / 4) / 256, 256>>>(edges);
    scan1_kernel<<<128, 256>>>();
    scan2_kernel<<<1, 128>>>();
    scan3_kernel<<<128, 256>>>();
    fill_adj<<<(B_ * E_ / 4) / 256, 256>>>(edges, types);

    dim3 grid(NBLK, M_TOT / 128);   // (18, 256)
    // layer 0
    rgcn_gemm_mma<<<grid, 256, SMEM_DYN>>>(xh, bh, bias, y0, xw);
    aggregate_kernel<<<M_TOT / 8, 256>>>(xw, y0, xh);   // fused relu+fp16 convert
    // layer 1 (final)
    rgcn_gemm_mma<<<grid, 256, SMEM_DYN>>>(xh, bh1, bias + D_, out, xw);
    aggregate_kernel<<<M_TOT / 8, 256>>>(xw, out, nullptr);
}